// round 15
// baseline (speedup 1.0000x reference)
#include <cuda_runtime.h>
#include <cuda_bf16.h>
#include <math.h>
#include <float.h>
#include <stdint.h>

// ---------------- problem constants ----------------
#define TT      2048
#define HID     2048
#define NHEADS  8
#define HD      256
#define QS      2048
#define KVS     256
#define QKVN    2560
#define SCALING 0.0625f

// ---------------- scratch ----------------
// g_S doubles as: (early) qkv split-K partials [4][TT*QKVN] fp32 (84MB); (later) scores.
__device__ float g_S[(size_t)NHEADS * TT * TT];
__device__ float g_pv_part[4][(size_t)TT * QS];

__device__ __nv_bfloat16 g_hid_hi[(size_t)TT * HID],  g_hid_lo[(size_t)TT * HID];
__device__ __nv_bfloat16 g_wqkv_hi[(size_t)QKVN * HID], g_wqkv_lo[(size_t)QKVN * HID];
__device__ __nv_bfloat16 g_wo_hi[(size_t)HID * QS],   g_wo_lo[(size_t)HID * QS];
__device__ __nv_bfloat16 g_Q_hi[(size_t)NHEADS * TT * HD], g_Q_lo[(size_t)NHEADS * TT * HD];
__device__ __nv_bfloat16 g_K_hi[(size_t)TT * HD],     g_K_lo[(size_t)TT * HD];
__device__ __nv_bfloat16 g_Vt_hi[(size_t)HD * TT],    g_Vt_lo[(size_t)HD * TT];
__device__ __nv_bfloat16 g_P_hi[(size_t)NHEADS * TT * TT], g_P_lo[(size_t)NHEADS * TT * TT];
__device__ __nv_bfloat16 g_attn_hi[(size_t)TT * QS],  g_attn_lo[(size_t)TT * QS];

// ---------------- baseline-PTX helpers ----------------
__device__ __forceinline__ uint32_t smem_to_u32(const void* p) {
    uint32_t a;
    asm("{ .reg .u64 t; cvta.to.shared.u64 t, %1; cvt.u32.u64 %0, t; }" : "=r"(a) : "l"(p));
    return a;
}
#define CP_ASYNC16(dst, src) \
    asm volatile("cp.async.cg.shared.global [%0], [%1], 16;" :: "r"(dst), "l"(src) : "memory")
#define CP_COMMIT() asm volatile("cp.async.commit_group;" ::: "memory")
#define CP_WAIT1()  asm volatile("cp.async.wait_group 1;" ::: "memory")
#define CP_WAIT0()  asm volatile("cp.async.wait_group 0;" ::: "memory")

__device__ __forceinline__ void ldsm_x4(uint32_t& r0, uint32_t& r1, uint32_t& r2, uint32_t& r3,
                                        uint32_t addr) {
    asm volatile("ldmatrix.sync.aligned.m8n8.x4.shared.b16 {%0,%1,%2,%3}, [%4];"
                 : "=r"(r0), "=r"(r1), "=r"(r2), "=r"(r3) : "r"(addr));
}
__device__ __forceinline__ void mma_bf16(float* d, const uint32_t* a, const uint32_t* b) {
    asm volatile("mma.sync.aligned.m16n8k16.row.col.f32.bf16.bf16.f32 "
                 "{%0,%1,%2,%3}, {%4,%5,%6,%7}, {%8,%9}, {%0,%1,%2,%3};"
                 : "+f"(d[0]), "+f"(d[1]), "+f"(d[2]), "+f"(d[3])
                 : "r"(a[0]), "r"(a[1]), "r"(a[2]), "r"(a[3]), "r"(b[0]), "r"(b[1]));
}

__device__ __forceinline__ uint32_t sw_addr(uint32_t plane_base, int row, int chunk) {
    return plane_base + row * 64 + ((chunk ^ ((row >> 1) & 3)) << 4);
}
#define NSTG 3

// ============================================================
// 3xBF16 warp-MMA GEMM:  C = alpha * A * B^T
// Block tile (MT*64) x (XP*128); XP>1 runs XP 128-col phases over ONE
// continuous cp.async pipeline (single warmup; phase epilogues overlap the
// next phase's prefetch). BK=32, 8 warps; MT=2 -> 96KB smem, 2 CTAs/SM.
// CAUSAL + XP>1: masked phases are skipped exactly (nph from geometry).
// NSPLIT>1: K split into NSPLIT 32-aligned pieces; partial s -> C + s*sSplit.
// EXACT WAIT: WAIT1 unless last chunk (then WAIT0) — load-bearing for small
//   nct and final-chunk ordering.
// ============================================================
template<bool CAUSAL, bool CAUSAL_K, int MT, int NSPLIT, int XP>
__global__ void __launch_bounds__(256, 2) gemm_mma3(
    const __nv_bfloat16* __restrict__ Ahi, const __nv_bfloat16* __restrict__ Alo,
    const __nv_bfloat16* __restrict__ Bhi, const __nv_bfloat16* __restrict__ Blo,
    float* __restrict__ C, __nv_bfloat16* __restrict__ Chi, __nv_bfloat16* __restrict__ Clo,
    int K, int lda, int ldb, int ldc, float alpha,
    size_t sAz, size_t sBz, size_t sCz, size_t sSplit)
{
    constexpr int APLANE = MT * 4096;
    constexpr int STAGEB = 2 * APLANE + 16384;
    constexpr int ASLOTS = MT * 256;
    constexpr bool YREV = (NSPLIT > 1) || (CAUSAL && XP > 1);

    int zz = blockIdx.z, split = 0;
    if (NSPLIT > 1) { split = zz % NSPLIT; zz /= NSPLIT; }
    const int by = YREV ? (gridDim.y - 1 - blockIdx.y) : blockIdx.y;
    const int r0 = by * (MT * 64);
    const int c0 = blockIdx.x * (XP * 128);
    if (CAUSAL && c0 > r0 + MT * 64 - 1) return;

    extern __shared__ char smem[];
    const uint32_t sb = smem_to_u32(smem);

    const int tid  = threadIdx.x;
    const int lane = tid & 31;
    const int wid  = tid >> 5;
    const int wr   = wid >> 1;
    const int wc   = wid & 1;

    const __nv_bfloat16* gp[4];
    gp[0] = Ahi + zz * sAz + (size_t)r0 * lda;
    gp[1] = Alo + zz * sAz + (size_t)r0 * lda;
    gp[2] = Bhi + zz * sBz + (size_t)c0 * ldb;
    gp[3] = Blo + zz * sBz + (size_t)c0 * ldb;
    const int ldp[4] = {lda, lda, ldb, ldb};

    const int len = CAUSAL_K ? (r0 + MT * 64) : K;
    int kBeg = 0, kEnd = len;
    if (NSPLIT > 1) {
        const int per = (len / NSPLIT) & ~31;
        kBeg = split * per;
        kEnd = (split == NSPLIT - 1) ? len : kBeg + per;
    }
    const int ncp = (kEnd - kBeg) >> 5;          // chunks per phase

    int nph = XP;
    if (CAUSAL && XP > 1) {
        const int np = (r0 + MT * 64 - 1 - c0) / 128 + 1;
        nph = (np < XP) ? np : XP;
        if (nph < 1) nph = 1;
    }
    const int nct = nph * ncp;                   // total chunks

    float acc[MT][8][4];
    #pragma unroll
    for (int mi = 0; mi < MT; mi++)
        #pragma unroll
        for (int ni = 0; ni < 8; ni++)
            #pragma unroll
            for (int e = 0; e < 4; e++) acc[mi][ni][e] = 0.f;

    // prefetch global chunk jc into stage jc%NSTG
    auto prefetch = [&](int jc) {
        const int ph = (XP > 1) ? (jc / ncp) : 0;
        const int k0 = kBeg + ((jc - ph * ncp) << 5);
        const size_t boff = (size_t)ph * 128 * ldb;
        const int st = jc % NSTG;
        const int total = 2 * ASLOTS + 1024;
        #pragma unroll
        for (int s = tid; s < total; s += 256) {
            int p, idx;
            if (s < 2 * ASLOTS) { p = s / ASLOTS; idx = s - p * ASLOTS; }
            else { const int s2 = s - 2 * ASLOTS; p = 2 + (s2 >> 9); idx = s2 & 511; }
            const int row = idx >> 2, chunk = idx & 3;
            const uint32_t pbase = sb + st * STAGEB +
                (p < 2 ? p * APLANE : 2 * APLANE + (p - 2) * 8192);
            const __nv_bfloat16* src = gp[p] + (size_t)row * ldp[p] + k0 + chunk * 8
                                       + (p >= 2 ? boff : 0);
            CP_ASYNC16(sw_addr(pbase, row, chunk), src);
        }
        CP_COMMIT();
    };

    int pf = 0;
    prefetch(0); pf = 1;
    if (nct > 1) { prefetch(1); pf = 2; }

    const int ldj = lane >> 3;
    const int ldr = lane & 7;
    const int g = lane >> 2;
    const int t = lane & 3;

    const bool wantF32 = (C != nullptr);
    float* Cb = C;
    if (NSPLIT > 1 && wantF32) Cb += (size_t)split * sSplit;

    int jc = 0;
    for (int ph = 0; ph < nph; ph++) {
        if (XP > 1 && ph > 0) {
            #pragma unroll
            for (int mi = 0; mi < MT; mi++)
                #pragma unroll
                for (int ni = 0; ni < 8; ni++)
                    #pragma unroll
                    for (int e = 0; e < 4; e++) acc[mi][ni][e] = 0.f;
        }

        for (int jj = 0; jj < ncp; jj++, jc++) {
            if (jc + 1 < nct) { CP_WAIT1(); } else { CP_WAIT0(); }   // exact wait
            __syncthreads();
            if (pf < nct) { prefetch(pf); pf++; }

            const int st = jc % NSTG;
            const uint32_t Ab = sb + st * STAGEB;
            const uint32_t Al = Ab + APLANE;
            const uint32_t Bb = Ab + 2 * APLANE;
            const uint32_t Bl = Bb + 8192;

            #pragma unroll
            for (int ks = 0; ks < 2; ks++) {
                uint32_t ah[MT][4], al[MT][4];
                #pragma unroll
                for (int mi = 0; mi < MT; mi++) {
                    const int row = wr * (MT * 16) + mi * 16 + (ldj & 1) * 8 + ldr;
                    const int ch  = ks * 2 + (ldj >> 1);
                    ldsm_x4(ah[mi][0], ah[mi][1], ah[mi][2], ah[mi][3], sw_addr(Ab, row, ch));
                    ldsm_x4(al[mi][0], al[mi][1], al[mi][2], al[mi][3], sw_addr(Al, row, ch));
                }
                #pragma unroll
                for (int h2 = 0; h2 < 2; h2++) {
                    uint32_t bh[4][2], bl[4][2];
                    #pragma unroll
                    for (int pi = 0; pi < 2; pi++) {
                        const int row = wc * 64 + h2 * 32 + pi * 16 + (ldj >> 1) * 8 + ldr;
                        const int ch  = ks * 2 + (ldj & 1);
                        ldsm_x4(bh[2 * pi][0], bh[2 * pi][1], bh[2 * pi + 1][0], bh[2 * pi + 1][1],
                                sw_addr(Bb, row, ch));
                        ldsm_x4(bl[2 * pi][0], bl[2 * pi][1], bl[2 * pi + 1][0], bl[2 * pi + 1][1],
                                sw_addr(Bl, row, ch));
                    }
                    #pragma unroll
                    for (int mi = 0; mi < MT; mi++)
                        #pragma unroll
                        for (int nl = 0; nl < 4; nl++)
                            mma_bf16(acc[mi][h2 * 4 + nl], ah[mi], bh[nl]);
                    #pragma unroll
                    for (int mi = 0; mi < MT; mi++)
                        #pragma unroll
                        for (int nl = 0; nl < 4; nl++)
                            mma_bf16(acc[mi][h2 * 4 + nl], ah[mi], bl[nl]);
                    #pragma unroll
                    for (int mi = 0; mi < MT; mi++)
                        #pragma unroll
                        for (int nl = 0; nl < 4; nl++)
                            mma_bf16(acc[mi][h2 * 4 + nl], al[mi], bh[nl]);
                }
            }
        }

        // ---- epilogue for this phase (register-only; overlaps next-phase prefetch) ----
        const int cbase = c0 + ph * 128;
        #pragma unroll
        for (int mi = 0; mi < MT; mi++) {
            #pragma unroll
            for (int ni = 0; ni < 8; ni++) {
                const int rr = r0 + wr * (MT * 16) + mi * 16 + g;
                const int cc = cbase + wc * 64 + ni * 8 + t * 2;
                #pragma unroll
                for (int half = 0; half < 2; half++) {
                    const int r = rr + half * 8;
                    float v0 = alpha * acc[mi][ni][half * 2 + 0];
                    float v1 = alpha * acc[mi][ni][half * 2 + 1];
                    if (CAUSAL) {
                        if (cc + 0 > r) v0 = 0.f;
                        if (cc + 1 > r) v1 = 0.f;
                    }
                    if (wantF32) {
                        float2 v; v.x = v0; v.y = v1;
                        *(float2*)(Cb + zz * sCz + (size_t)r * ldc + cc) = v;
                    } else {
                        const __nv_bfloat16 h0 = __float2bfloat16(v0);
                        const __nv_bfloat16 h1 = __float2bfloat16(v1);
                        __nv_bfloat162 hv; hv.x = h0; hv.y = h1;
                        __nv_bfloat162 lv;
                        lv.x = __float2bfloat16(v0 - __bfloat162float(h0));
                        lv.y = __float2bfloat16(v1 - __bfloat162float(h1));
                        *(__nv_bfloat162*)(Chi + zz * sCz + (size_t)r * ldc + cc) = hv;
                        *(__nv_bfloat162*)(Clo + zz * sCz + (size_t)r * ldc + cc) = lv;
                    }
                }
            }
        }
    }
}

// ============================================================
// Fused fp32 -> bf16 hi/lo split for all three inputs (single launch)
// ============================================================
__global__ void conv_all(const float* __restrict__ s0, __nv_bfloat16* __restrict__ h0, __nv_bfloat16* __restrict__ l0, int n0,
                         const float* __restrict__ s1, __nv_bfloat16* __restrict__ h1, __nv_bfloat16* __restrict__ l1, int n1,
                         const float* __restrict__ s2, __nv_bfloat16* __restrict__ h2, __nv_bfloat16* __restrict__ l2, int n2)
{
    int i = blockIdx.x * blockDim.x + threadIdx.x;
    const float* s; __nv_bfloat16 *hh, *ll;
    if (i < n0) { s = s0; hh = h0; ll = l0; }
    else if (i < n0 + n1) { i -= n0; s = s1; hh = h1; ll = l1; }
    else if (i < n0 + n1 + n2) { i -= n0 + n1; s = s2; hh = h2; ll = l2; }
    else return;

    const float4 x = ((const float4*)s)[i];
    __nv_bfloat162 a0, a1, b0, b1;
    a0.x = __float2bfloat16(x.x); a0.y = __float2bfloat16(x.y);
    a1.x = __float2bfloat16(x.z); a1.y = __float2bfloat16(x.w);
    b0.x = __float2bfloat16(x.x - __bfloat162float(a0.x));
    b0.y = __float2bfloat16(x.y - __bfloat162float(a0.y));
    b1.x = __float2bfloat16(x.z - __bfloat162float(a1.x));
    b1.y = __float2bfloat16(x.w - __bfloat162float(a1.y));
    ((__nv_bfloat162*)hh)[2 * i]     = a0;
    ((__nv_bfloat162*)hh)[2 * i + 1] = a1;
    ((__nv_bfloat162*)ll)[2 * i]     = b0;
    ((__nv_bfloat162*)ll)[2 * i + 1] = b1;
}

// ============================================================
// sum of FOUR fp32 partials -> bf16 hi/lo planes (split-K x4 P*V)
// ============================================================
__global__ void addconv_planes4(const float* __restrict__ a, const float* __restrict__ b,
                                const float* __restrict__ c, const float* __restrict__ d,
                                __nv_bfloat16* __restrict__ hi, __nv_bfloat16* __restrict__ lo, int n4)
{
    const int i = blockIdx.x * blockDim.x + threadIdx.x;
    if (i < n4) {
        const float4 xa = ((const float4*)a)[i];
        const float4 xb = ((const float4*)b)[i];
        const float4 xc = ((const float4*)c)[i];
        const float4 xd = ((const float4*)d)[i];
        float x0 = (xa.x + xb.x) + (xc.x + xd.x);
        float x1 = (xa.y + xb.y) + (xc.y + xd.y);
        float x2 = (xa.z + xb.z) + (xc.z + xd.z);
        float x3 = (xa.w + xb.w) + (xc.w + xd.w);
        __nv_bfloat162 h0, h1, l0, l1;
        h0.x = __float2bfloat16(x0); h0.y = __float2bfloat16(x1);
        h1.x = __float2bfloat16(x2); h1.y = __float2bfloat16(x3);
        l0.x = __float2bfloat16(x0 - __bfloat162float(h0.x));
        l0.y = __float2bfloat16(x1 - __bfloat162float(h0.y));
        l1.x = __float2bfloat16(x2 - __bfloat162float(h1.x));
        l1.y = __float2bfloat16(x3 - __bfloat162float(h1.y));
        ((__nv_bfloat162*)hi)[2 * i]     = h0;
        ((__nv_bfloat162*)hi)[2 * i + 1] = h1;
        ((__nv_bfloat162*)lo)[2 * i]     = l0;
        ((__nv_bfloat162*)lo)[2 * i + 1] = l1;
    }
}

// ============================================================
// RoPE + split: sums the FOUR qkv split-K partials (in g_S) inline.
// ============================================================
__global__ void rope_split_planes(const int* __restrict__ positions)
{
    const int t = blockIdx.x, head = blockIdx.y, i = threadIdx.x;
    const float* p0 = g_S + (size_t)t * QKVN;
    const float* p1 = p0 + (size_t)TT * QKVN;
    const float* p2 = p1 + (size_t)TT * QKVN;
    const float* p3 = p2 + (size_t)TT * QKVN;

    if (head == 9) {
        #pragma unroll
        for (int hh = 0; hh < 2; hh++) {
            const int d = i + hh * 128;
            const int col = QS + KVS + d;
            const float x = (p0[col] + p1[col]) + (p2[col] + p3[col]);
            const __nv_bfloat16 h = __float2bfloat16(x);
            g_Vt_hi[(size_t)d * TT + t] = h;
            g_Vt_lo[(size_t)d * TT + t] = __float2bfloat16(x - __bfloat162float(h));
        }
        return;
    }

    const int cbase = (head < 8) ? head * HD : QS;
    const float pos = (float)positions[t];
    const float inv_freq = expf(-((float)(2 * i) / (float)HD) * logf(10000.0f));
    const float ang = pos * inv_freq;
    const float c = cosf(ang), s = sinf(ang);
    const int c1 = cbase + i, c2 = cbase + i + 128;
    const float x1 = (p0[c1] + p1[c1]) + (p2[c1] + p3[c1]);
    const float x2 = (p0[c2] + p1[c2]) + (p2[c2] + p3[c2]);
    const float o1 = x1 * c - x2 * s;
    const float o2 = x2 * c + x1 * s;

    __nv_bfloat16 *dh, *dl;
    size_t off;
    if (head < 8) { off = ((size_t)head * TT + t) * HD; dh = g_Q_hi; dl = g_Q_lo; }
    else          { off = (size_t)t * HD;               dh = g_K_hi; dl = g_K_lo; }

    __nv_bfloat16 h1 = __float2bfloat16(o1);
    dh[off + i] = h1;
    dl[off + i] = __float2bfloat16(o1 - __bfloat162float(h1));
    __nv_bfloat16 h2 = __float2bfloat16(o2);
    dh[off + i + 128] = h2;
    dl[off + i + 128] = __float2bfloat16(o2 - __bfloat162float(h2));
}

// ============================================================
// Causal softmax: warp-per-row, smem row cache.
// ============================================================
__global__ void __launch_bounds__(256, 2) softmax_planes()
{
    extern __shared__ float xs[];
    const int h = blockIdx.y;
    const int warp = threadIdx.x >> 5, lane = threadIdx.x & 31;
    const int q = blockIdx.x * 8 + warp;
    float* xrow = xs + warp * 2048;

    const float* row = g_S + ((size_t)h * TT + q) * TT;
    const int n = q + 1;
    const int npad = (q & ~127) + 128;

    float m = -FLT_MAX;
    for (int k = lane * 4; k < n; k += 128) {
        const float4 v = *(const float4*)(row + k);
        xrow[k + 0] = v.x; xrow[k + 1] = v.y; xrow[k + 2] = v.z; xrow[k + 3] = v.w;
        if (k + 0 < n) m = fmaxf(m, v.x);
        if (k + 1 < n) m = fmaxf(m, v.y);
        if (k + 2 < n) m = fmaxf(m, v.z);
        if (k + 3 < n) m = fmaxf(m, v.w);
    }
    #pragma unroll
    for (int o = 16; o > 0; o >>= 1) m = fmaxf(m, __shfl_xor_sync(0xFFFFFFFFu, m, o));

    float sum = 0.f;
    for (int k = lane * 4; k < n; k += 128) {
        #pragma unroll
        for (int j = 0; j < 4; j++) {
            const float e = (k + j < n) ? __expf(xrow[k + j] - m) : 0.f;
            xrow[k + j] = e;
            sum += e;
        }
    }
    #pragma unroll
    for (int o = 16; o > 0; o >>= 1) sum += __shfl_xor_sync(0xFFFFFFFFu, sum, o);
    const float inv = 1.0f / sum;

    __nv_bfloat16* ph = g_P_hi + ((size_t)h * TT + q) * TT;
    __nv_bfloat16* pl = g_P_lo + ((size_t)h * TT + q) * TT;
    for (int k = lane * 4; k < npad; k += 128) {
        __nv_bfloat162 hv0, lv0, hv1, lv1;
        #pragma unroll
        for (int j = 0; j < 4; j++) {
            const float p = (k + j < n) ? xrow[k + j] * inv : 0.f;
            const __nv_bfloat16 hb = __float2bfloat16(p);
            const __nv_bfloat16 lb = __float2bfloat16(p - __bfloat162float(hb));
            if (j == 0) { hv0.x = hb; lv0.x = lb; }
            if (j == 1) { hv0.y = hb; lv0.y = lb; }
            if (j == 2) { hv1.x = hb; lv1.x = lb; }
            if (j == 3) { hv1.y = hb; lv1.y = lb; }
        }
        *(__nv_bfloat162*)(ph + k)     = hv0;
        *(__nv_bfloat162*)(ph + k + 2) = hv1;
        *(__nv_bfloat162*)(pl + k)     = lv0;
        *(__nv_bfloat162*)(pl + k + 2) = lv1;
    }
}

// ============================================================
extern "C" void kernel_launch(void* const* d_in, const int* in_sizes, int n_in,
                              void* d_out, int out_size)
{
    const int*   positions = (const int*)d_in[0];
    const float* hidden    = (const float*)d_in[1];
    const float* Wqkv      = (const float*)d_in[2];
    const float* Wo        = (const float*)d_in[3];
    float*       out       = (float*)d_out;

    float *S, *pvp;
    __nv_bfloat16 *hh, *hl, *wqh, *wql, *woh, *wol, *Qh, *Ql, *Kh, *Kl, *Vth, *Vtl,
                  *Ph, *Pl, *Ath, *Atl;
    cudaGetSymbolAddress((void**)&S,   g_S);
    cudaGetSymbolAddress((void**)&pvp, g_pv_part);
    cudaGetSymbolAddress((void**)&hh,  g_hid_hi);  cudaGetSymbolAddress((void**)&hl,  g_hid_lo);
    cudaGetSymbolAddress((void**)&wqh, g_wqkv_hi); cudaGetSymbolAddress((void**)&wql, g_wqkv_lo);
    cudaGetSymbolAddress((void**)&woh, g_wo_hi);   cudaGetSymbolAddress((void**)&wol, g_wo_lo);
    cudaGetSymbolAddress((void**)&Qh,  g_Q_hi);    cudaGetSymbolAddress((void**)&Ql,  g_Q_lo);
    cudaGetSymbolAddress((void**)&Kh,  g_K_hi);    cudaGetSymbolAddress((void**)&Kl,  g_K_lo);
    cudaGetSymbolAddress((void**)&Vth, g_Vt_hi);   cudaGetSymbolAddress((void**)&Vtl, g_Vt_lo);
    cudaGetSymbolAddress((void**)&Ph,  g_P_hi);    cudaGetSymbolAddress((void**)&Pl,  g_P_lo);
    cudaGetSymbolAddress((void**)&Ath, g_attn_hi); cudaGetSymbolAddress((void**)&Atl, g_attn_lo);

    const int SMEM_MT2 = NSTG * (2 * 8192 + 16384);   // 98304

    cudaFuncSetAttribute(gemm_mma3<false, false, 2, 4, 1>, cudaFuncAttributeMaxDynamicSharedMemorySize, SMEM_MT2);
    cudaFuncSetAttribute(gemm_mma3<true,  false, 2, 1, 2>, cudaFuncAttributeMaxDynamicSharedMemorySize, SMEM_MT2);
    cudaFuncSetAttribute(gemm_mma3<false, true,  2, 4, 2>, cudaFuncAttributeMaxDynamicSharedMemorySize, SMEM_MT2);
    cudaFuncSetAttribute(gemm_mma3<false, false, 2, 1, 1>, cudaFuncAttributeMaxDynamicSharedMemorySize, SMEM_MT2);
    cudaFuncSetAttribute(softmax_planes, cudaFuncAttributeMaxDynamicSharedMemorySize, 65536);

    // 0) fp32 -> bf16 hi/lo planes (single fused launch)
    {
        int n0 = TT * HID / 4, n1 = QKVN * HID / 4, n2 = HID * QS / 4;
        int tot = n0 + n1 + n2;
        conv_all<<<(tot + 255) / 256, 256>>>(hidden, hh, hl, n0,
                                             Wqkv, wqh, wql, n1,
                                             Wo, woh, wol, n2);
    }

    // 1) qkv partials = hidden @ Wqkv^T (split-K x4, 1280 CTAs)
    gemm_mma3<false, false, 2, 4, 1><<<dim3(QKVN / 128, TT / 128, 4), 256, SMEM_MT2>>>(
        hh, hl, wqh, wql, S, nullptr, nullptr,
        HID, HID, HID, QKVN, 1.0f, 0, 0, 0, (size_t)TT * QKVN);

    // 2) RoPE + 4-partial sum + plane split (V transposed)
    rope_split_planes<<<dim3(TT, 10), 128>>>(positions);

    // 3) scores = scale * Q @ K^T (causal, XPAIR: 256-col CTAs, one warmup) -> g_S
    gemm_mma3<true, false, 2, 1, 2><<<dim3(TT / 256, TT / 128, NHEADS), 256, SMEM_MT2>>>(
        Qh, Ql, Kh, Kl, S, nullptr, nullptr,
        HD, HD, HD, TT, SCALING, (size_t)TT * HD, 0, (size_t)TT * TT, 0);

    // 4) softmax -> P planes
    softmax_planes<<<dim3(TT / 8, NHEADS), 256, 65536>>>();

    // 5) attn partials = P @ Vt^T (block-causal K, split-K x4, XP=2 over the
    //    256 output columns -> 512 CTAs, 2..32 chunks each, single warmup)
    gemm_mma3<false, true, 2, 4, 2><<<dim3(HD / 256, TT / 128, NHEADS * 4), 256, SMEM_MT2>>>(
        Ph, Pl, Vth, Vtl, pvp, nullptr, nullptr,
        TT, TT, TT, QS, 1.0f, (size_t)TT * TT, 0, (size_t)HD, (size_t)TT * QS);

    // 5b) attn = sum of 4 partials -> bf16 hi/lo planes
    {
        int n4 = TT * QS / 4;
        const size_t P = (size_t)TT * QS;
        addconv_planes4<<<(n4 + 255) / 256, 256>>>(pvp, pvp + P, pvp + 2 * P, pvp + 3 * P,
                                                   Ath, Atl, n4);
    }

    // 6) out = attn @ Wo^T
    gemm_mma3<false, false, 2, 1, 1><<<dim3(HID / 128, TT / 128, 1), 256, SMEM_MT2>>>(
        Ath, Atl, woh, wol, out, nullptr, nullptr,
        QS, QS, QS, HID, 1.0f, 0, 0, 0, 0);
}

// round 16
// speedup vs baseline: 1.0468x; 1.0468x over previous
#include <cuda_runtime.h>
#include <cuda_bf16.h>
#include <math.h>
#include <float.h>
#include <stdint.h>

// ---------------- problem constants ----------------
#define TT      2048
#define HID     2048
#define NHEADS  8
#define HD      256
#define QS      2048
#define KVS     256
#define QKVN    2560
#define SCALING 0.0625f

// ---------------- scratch ----------------
// g_S doubles as: (early) qkv split-K partials [4][TT*QKVN] fp32 (84MB); (later) scores.
__device__ float g_S[(size_t)NHEADS * TT * TT];
__device__ float g_pv_part[4][(size_t)TT * QS];

__device__ __nv_bfloat16 g_hid_hi[(size_t)TT * HID],  g_hid_lo[(size_t)TT * HID];
__device__ __nv_bfloat16 g_wqkv_hi[(size_t)QKVN * HID], g_wqkv_lo[(size_t)QKVN * HID];
__device__ __nv_bfloat16 g_wo_hi[(size_t)HID * QS],   g_wo_lo[(size_t)HID * QS];
__device__ __nv_bfloat16 g_Q_hi[(size_t)NHEADS * TT * HD], g_Q_lo[(size_t)NHEADS * TT * HD];
__device__ __nv_bfloat16 g_K_hi[(size_t)TT * HD],     g_K_lo[(size_t)TT * HD];
__device__ __nv_bfloat16 g_Vt_hi[(size_t)HD * TT],    g_Vt_lo[(size_t)HD * TT];
__device__ __nv_bfloat16 g_P_hi[(size_t)NHEADS * TT * TT], g_P_lo[(size_t)NHEADS * TT * TT];
__device__ __nv_bfloat16 g_attn_hi[(size_t)TT * QS],  g_attn_lo[(size_t)TT * QS];

// ---------------- baseline-PTX helpers ----------------
__device__ __forceinline__ uint32_t smem_to_u32(const void* p) {
    uint32_t a;
    asm("{ .reg .u64 t; cvta.to.shared.u64 t, %1; cvt.u32.u64 %0, t; }" : "=r"(a) : "l"(p));
    return a;
}
#define CP_ASYNC16(dst, src) \
    asm volatile("cp.async.cg.shared.global [%0], [%1], 16;" :: "r"(dst), "l"(src) : "memory")
#define CP_COMMIT() asm volatile("cp.async.commit_group;" ::: "memory")
#define CP_WAIT1()  asm volatile("cp.async.wait_group 1;" ::: "memory")
#define CP_WAIT0()  asm volatile("cp.async.wait_group 0;" ::: "memory")

__device__ __forceinline__ void ldsm_x4(uint32_t& r0, uint32_t& r1, uint32_t& r2, uint32_t& r3,
                                        uint32_t addr) {
    asm volatile("ldmatrix.sync.aligned.m8n8.x4.shared.b16 {%0,%1,%2,%3}, [%4];"
                 : "=r"(r0), "=r"(r1), "=r"(r2), "=r"(r3) : "r"(addr));
}
__device__ __forceinline__ void mma_bf16(float* d, const uint32_t* a, const uint32_t* b) {
    asm volatile("mma.sync.aligned.m16n8k16.row.col.f32.bf16.bf16.f32 "
                 "{%0,%1,%2,%3}, {%4,%5,%6,%7}, {%8,%9}, {%0,%1,%2,%3};"
                 : "+f"(d[0]), "+f"(d[1]), "+f"(d[2]), "+f"(d[3])
                 : "r"(a[0]), "r"(a[1]), "r"(a[2]), "r"(a[3]), "r"(b[0]), "r"(b[1]));
}

__device__ __forceinline__ uint32_t sw_addr(uint32_t plane_base, int row, int chunk) {
    return plane_base + row * 64 + ((chunk ^ ((row >> 1) & 3)) << 4);
}
#define NSTG 3

// ============================================================
// 3xBF16 warp-MMA GEMM:  C = alpha * A * B^T
// Block tile (MT*64) x (XP*128); XP>1 runs XP 128-col phases over ONE
// continuous cp.async pipeline (single warmup; phase epilogues overlap the
// next phase's prefetch). BK=32, 8 warps; MT=2 -> 96KB smem, 2 CTAs/SM.
// CAUSAL + XP>1: masked phases skipped exactly; y reversed (big tiles first).
// NSPLIT>1: K split into NSPLIT 32-aligned pieces; partial s -> C + s*sSplit.
// EXACT WAIT: WAIT1 unless last chunk (then WAIT0) — load-bearing for small
//   nct and final-chunk ordering.
// Scheduling law (R13/R14/R15 evidence): prefer many small uniform CTAs;
//   phase-merge only over-subscribed uniform grids (scores XP=2 good;
//   XP=4 scores / XP=2 PV bad).
// ============================================================
template<bool CAUSAL, bool CAUSAL_K, int MT, int NSPLIT, int XP>
__global__ void __launch_bounds__(256, 2) gemm_mma3(
    const __nv_bfloat16* __restrict__ Ahi, const __nv_bfloat16* __restrict__ Alo,
    const __nv_bfloat16* __restrict__ Bhi, const __nv_bfloat16* __restrict__ Blo,
    float* __restrict__ C, __nv_bfloat16* __restrict__ Chi, __nv_bfloat16* __restrict__ Clo,
    int K, int lda, int ldb, int ldc, float alpha,
    size_t sAz, size_t sBz, size_t sCz, size_t sSplit)
{
    constexpr int APLANE = MT * 4096;
    constexpr int STAGEB = 2 * APLANE + 16384;
    constexpr int ASLOTS = MT * 256;
    constexpr bool YREV = (NSPLIT > 1) || (CAUSAL && XP > 1);

    int zz = blockIdx.z, split = 0;
    if (NSPLIT > 1) { split = zz % NSPLIT; zz /= NSPLIT; }
    const int by = YREV ? (gridDim.y - 1 - blockIdx.y) : blockIdx.y;
    const int r0 = by * (MT * 64);
    const int c0 = blockIdx.x * (XP * 128);
    if (CAUSAL && c0 > r0 + MT * 64 - 1) return;

    extern __shared__ char smem[];
    const uint32_t sb = smem_to_u32(smem);

    const int tid  = threadIdx.x;
    const int lane = tid & 31;
    const int wid  = tid >> 5;
    const int wr   = wid >> 1;
    const int wc   = wid & 1;

    const __nv_bfloat16* gp[4];
    gp[0] = Ahi + zz * sAz + (size_t)r0 * lda;
    gp[1] = Alo + zz * sAz + (size_t)r0 * lda;
    gp[2] = Bhi + zz * sBz + (size_t)c0 * ldb;
    gp[3] = Blo + zz * sBz + (size_t)c0 * ldb;
    const int ldp[4] = {lda, lda, ldb, ldb};

    const int len = CAUSAL_K ? (r0 + MT * 64) : K;
    int kBeg = 0, kEnd = len;
    if (NSPLIT > 1) {
        const int per = (len / NSPLIT) & ~31;
        kBeg = split * per;
        kEnd = (split == NSPLIT - 1) ? len : kBeg + per;
    }
    const int ncp = (kEnd - kBeg) >> 5;          // chunks per phase

    int nph = XP;
    if (CAUSAL && XP > 1) {
        const int np = (r0 + MT * 64 - 1 - c0) / 128 + 1;
        nph = (np < XP) ? np : XP;
        if (nph < 1) nph = 1;
    }
    const int nct = nph * ncp;                   // total chunks

    float acc[MT][8][4];
    #pragma unroll
    for (int mi = 0; mi < MT; mi++)
        #pragma unroll
        for (int ni = 0; ni < 8; ni++)
            #pragma unroll
            for (int e = 0; e < 4; e++) acc[mi][ni][e] = 0.f;

    // prefetch global chunk jc into stage jc%NSTG
    auto prefetch = [&](int jc) {
        const int ph = (XP > 1) ? (jc / ncp) : 0;
        const int k0 = kBeg + ((jc - ph * ncp) << 5);
        const size_t boff = (size_t)ph * 128 * ldb;
        const int st = jc % NSTG;
        const int total = 2 * ASLOTS + 1024;
        #pragma unroll
        for (int s = tid; s < total; s += 256) {
            int p, idx;
            if (s < 2 * ASLOTS) { p = s / ASLOTS; idx = s - p * ASLOTS; }
            else { const int s2 = s - 2 * ASLOTS; p = 2 + (s2 >> 9); idx = s2 & 511; }
            const int row = idx >> 2, chunk = idx & 3;
            const uint32_t pbase = sb + st * STAGEB +
                (p < 2 ? p * APLANE : 2 * APLANE + (p - 2) * 8192);
            const __nv_bfloat16* src = gp[p] + (size_t)row * ldp[p] + k0 + chunk * 8
                                       + (p >= 2 ? boff : 0);
            CP_ASYNC16(sw_addr(pbase, row, chunk), src);
        }
        CP_COMMIT();
    };

    int pf = 0;
    prefetch(0); pf = 1;
    if (nct > 1) { prefetch(1); pf = 2; }

    const int ldj = lane >> 3;
    const int ldr = lane & 7;
    const int g = lane >> 2;
    const int t = lane & 3;

    const bool wantF32 = (C != nullptr);
    float* Cb = C;
    if (NSPLIT > 1 && wantF32) Cb += (size_t)split * sSplit;

    int jc = 0;
    for (int ph = 0; ph < nph; ph++) {
        if (XP > 1 && ph > 0) {
            #pragma unroll
            for (int mi = 0; mi < MT; mi++)
                #pragma unroll
                for (int ni = 0; ni < 8; ni++)
                    #pragma unroll
                    for (int e = 0; e < 4; e++) acc[mi][ni][e] = 0.f;
        }

        for (int jj = 0; jj < ncp; jj++, jc++) {
            if (jc + 1 < nct) { CP_WAIT1(); } else { CP_WAIT0(); }   // exact wait
            __syncthreads();
            if (pf < nct) { prefetch(pf); pf++; }

            const int st = jc % NSTG;
            const uint32_t Ab = sb + st * STAGEB;
            const uint32_t Al = Ab + APLANE;
            const uint32_t Bb = Ab + 2 * APLANE;
            const uint32_t Bl = Bb + 8192;

            #pragma unroll
            for (int ks = 0; ks < 2; ks++) {
                uint32_t ah[MT][4], al[MT][4];
                #pragma unroll
                for (int mi = 0; mi < MT; mi++) {
                    const int row = wr * (MT * 16) + mi * 16 + (ldj & 1) * 8 + ldr;
                    const int ch  = ks * 2 + (ldj >> 1);
                    ldsm_x4(ah[mi][0], ah[mi][1], ah[mi][2], ah[mi][3], sw_addr(Ab, row, ch));
                    ldsm_x4(al[mi][0], al[mi][1], al[mi][2], al[mi][3], sw_addr(Al, row, ch));
                }
                #pragma unroll
                for (int h2 = 0; h2 < 2; h2++) {
                    uint32_t bh[4][2], bl[4][2];
                    #pragma unroll
                    for (int pi = 0; pi < 2; pi++) {
                        const int row = wc * 64 + h2 * 32 + pi * 16 + (ldj >> 1) * 8 + ldr;
                        const int ch  = ks * 2 + (ldj & 1);
                        ldsm_x4(bh[2 * pi][0], bh[2 * pi][1], bh[2 * pi + 1][0], bh[2 * pi + 1][1],
                                sw_addr(Bb, row, ch));
                        ldsm_x4(bl[2 * pi][0], bl[2 * pi][1], bl[2 * pi + 1][0], bl[2 * pi + 1][1],
                                sw_addr(Bl, row, ch));
                    }
                    #pragma unroll
                    for (int mi = 0; mi < MT; mi++)
                        #pragma unroll
                        for (int nl = 0; nl < 4; nl++)
                            mma_bf16(acc[mi][h2 * 4 + nl], ah[mi], bh[nl]);
                    #pragma unroll
                    for (int mi = 0; mi < MT; mi++)
                        #pragma unroll
                        for (int nl = 0; nl < 4; nl++)
                            mma_bf16(acc[mi][h2 * 4 + nl], ah[mi], bl[nl]);
                    #pragma unroll
                    for (int mi = 0; mi < MT; mi++)
                        #pragma unroll
                        for (int nl = 0; nl < 4; nl++)
                            mma_bf16(acc[mi][h2 * 4 + nl], al[mi], bh[nl]);
                }
            }
        }

        // ---- epilogue for this phase (register-only; overlaps next-phase prefetch) ----
        const int cbase = c0 + ph * 128;
        #pragma unroll
        for (int mi = 0; mi < MT; mi++) {
            #pragma unroll
            for (int ni = 0; ni < 8; ni++) {
                const int rr = r0 + wr * (MT * 16) + mi * 16 + g;
                const int cc = cbase + wc * 64 + ni * 8 + t * 2;
                #pragma unroll
                for (int half = 0; half < 2; half++) {
                    const int r = rr + half * 8;
                    float v0 = alpha * acc[mi][ni][half * 2 + 0];
                    float v1 = alpha * acc[mi][ni][half * 2 + 1];
                    if (CAUSAL) {
                        if (cc + 0 > r) v0 = 0.f;
                        if (cc + 1 > r) v1 = 0.f;
                    }
                    if (wantF32) {
                        float2 v; v.x = v0; v.y = v1;
                        *(float2*)(Cb + zz * sCz + (size_t)r * ldc + cc) = v;
                    } else {
                        const __nv_bfloat16 h0 = __float2bfloat16(v0);
                        const __nv_bfloat16 h1 = __float2bfloat16(v1);
                        __nv_bfloat162 hv; hv.x = h0; hv.y = h1;
                        __nv_bfloat162 lv;
                        lv.x = __float2bfloat16(v0 - __bfloat162float(h0));
                        lv.y = __float2bfloat16(v1 - __bfloat162float(h1));
                        *(__nv_bfloat162*)(Chi + zz * sCz + (size_t)r * ldc + cc) = hv;
                        *(__nv_bfloat162*)(Clo + zz * sCz + (size_t)r * ldc + cc) = lv;
                    }
                }
            }
        }
    }
}

// ============================================================
// Fused fp32 -> bf16 hi/lo split for all three inputs (single launch)
// ============================================================
__global__ void conv_all(const float* __restrict__ s0, __nv_bfloat16* __restrict__ h0, __nv_bfloat16* __restrict__ l0, int n0,
                         const float* __restrict__ s1, __nv_bfloat16* __restrict__ h1, __nv_bfloat16* __restrict__ l1, int n1,
                         const float* __restrict__ s2, __nv_bfloat16* __restrict__ h2, __nv_bfloat16* __restrict__ l2, int n2)
{
    int i = blockIdx.x * blockDim.x + threadIdx.x;
    const float* s; __nv_bfloat16 *hh, *ll;
    if (i < n0) { s = s0; hh = h0; ll = l0; }
    else if (i < n0 + n1) { i -= n0; s = s1; hh = h1; ll = l1; }
    else if (i < n0 + n1 + n2) { i -= n0 + n1; s = s2; hh = h2; ll = l2; }
    else return;

    const float4 x = ((const float4*)s)[i];
    __nv_bfloat162 a0, a1, b0, b1;
    a0.x = __float2bfloat16(x.x); a0.y = __float2bfloat16(x.y);
    a1.x = __float2bfloat16(x.z); a1.y = __float2bfloat16(x.w);
    b0.x = __float2bfloat16(x.x - __bfloat162float(a0.x));
    b0.y = __float2bfloat16(x.y - __bfloat162float(a0.y));
    b1.x = __float2bfloat16(x.z - __bfloat162float(a1.x));
    b1.y = __float2bfloat16(x.w - __bfloat162float(a1.y));
    ((__nv_bfloat162*)hh)[2 * i]     = a0;
    ((__nv_bfloat162*)hh)[2 * i + 1] = a1;
    ((__nv_bfloat162*)ll)[2 * i]     = b0;
    ((__nv_bfloat162*)ll)[2 * i + 1] = b1;
}

// ============================================================
// sum of FOUR fp32 partials -> bf16 hi/lo planes (split-K x4 P*V)
// ============================================================
__global__ void addconv_planes4(const float* __restrict__ a, const float* __restrict__ b,
                                const float* __restrict__ c, const float* __restrict__ d,
                                __nv_bfloat16* __restrict__ hi, __nv_bfloat16* __restrict__ lo, int n4)
{
    const int i = blockIdx.x * blockDim.x + threadIdx.x;
    if (i < n4) {
        const float4 xa = ((const float4*)a)[i];
        const float4 xb = ((const float4*)b)[i];
        const float4 xc = ((const float4*)c)[i];
        const float4 xd = ((const float4*)d)[i];
        float x0 = (xa.x + xb.x) + (xc.x + xd.x);
        float x1 = (xa.y + xb.y) + (xc.y + xd.y);
        float x2 = (xa.z + xb.z) + (xc.z + xd.z);
        float x3 = (xa.w + xb.w) + (xc.w + xd.w);
        __nv_bfloat162 h0, h1, l0, l1;
        h0.x = __float2bfloat16(x0); h0.y = __float2bfloat16(x1);
        h1.x = __float2bfloat16(x2); h1.y = __float2bfloat16(x3);
        l0.x = __float2bfloat16(x0 - __bfloat162float(h0.x));
        l0.y = __float2bfloat16(x1 - __bfloat162float(h0.y));
        l1.x = __float2bfloat16(x2 - __bfloat162float(h1.x));
        l1.y = __float2bfloat16(x3 - __bfloat162float(h1.y));
        ((__nv_bfloat162*)hi)[2 * i]     = h0;
        ((__nv_bfloat162*)hi)[2 * i + 1] = h1;
        ((__nv_bfloat162*)lo)[2 * i]     = l0;
        ((__nv_bfloat162*)lo)[2 * i + 1] = l1;
    }
}

// ============================================================
// RoPE + split: sums the FOUR qkv split-K partials (in g_S) inline.
// ============================================================
__global__ void rope_split_planes(const int* __restrict__ positions)
{
    const int t = blockIdx.x, head = blockIdx.y, i = threadIdx.x;
    const float* p0 = g_S + (size_t)t * QKVN;
    const float* p1 = p0 + (size_t)TT * QKVN;
    const float* p2 = p1 + (size_t)TT * QKVN;
    const float* p3 = p2 + (size_t)TT * QKVN;

    if (head == 9) {
        #pragma unroll
        for (int hh = 0; hh < 2; hh++) {
            const int d = i + hh * 128;
            const int col = QS + KVS + d;
            const float x = (p0[col] + p1[col]) + (p2[col] + p3[col]);
            const __nv_bfloat16 h = __float2bfloat16(x);
            g_Vt_hi[(size_t)d * TT + t] = h;
            g_Vt_lo[(size_t)d * TT + t] = __float2bfloat16(x - __bfloat162float(h));
        }
        return;
    }

    const int cbase = (head < 8) ? head * HD : QS;
    const float pos = (float)positions[t];
    const float inv_freq = expf(-((float)(2 * i) / (float)HD) * logf(10000.0f));
    const float ang = pos * inv_freq;
    const float c = cosf(ang), s = sinf(ang);
    const int c1 = cbase + i, c2 = cbase + i + 128;
    const float x1 = (p0[c1] + p1[c1]) + (p2[c1] + p3[c1]);
    const float x2 = (p0[c2] + p1[c2]) + (p2[c2] + p3[c2]);
    const float o1 = x1 * c - x2 * s;
    const float o2 = x2 * c + x1 * s;

    __nv_bfloat16 *dh, *dl;
    size_t off;
    if (head < 8) { off = ((size_t)head * TT + t) * HD; dh = g_Q_hi; dl = g_Q_lo; }
    else          { off = (size_t)t * HD;               dh = g_K_hi; dl = g_K_lo; }

    __nv_bfloat16 h1 = __float2bfloat16(o1);
    dh[off + i] = h1;
    dl[off + i] = __float2bfloat16(o1 - __bfloat162float(h1));
    __nv_bfloat16 h2 = __float2bfloat16(o2);
    dh[off + i + 128] = h2;
    dl[off + i + 128] = __float2bfloat16(o2 - __bfloat162float(h2));
}

// ============================================================
// Causal softmax: warp-per-row, smem row cache. 3 CTAs/SM (3x64KB = 192KB).
// ============================================================
__global__ void __launch_bounds__(256, 3) softmax_planes()
{
    extern __shared__ float xs[];
    const int h = blockIdx.y;
    const int warp = threadIdx.x >> 5, lane = threadIdx.x & 31;
    const int q = blockIdx.x * 8 + warp;
    float* xrow = xs + warp * 2048;

    const float* row = g_S + ((size_t)h * TT + q) * TT;
    const int n = q + 1;
    const int npad = (q & ~127) + 128;

    float m = -FLT_MAX;
    for (int k = lane * 4; k < n; k += 128) {
        const float4 v = *(const float4*)(row + k);
        xrow[k + 0] = v.x; xrow[k + 1] = v.y; xrow[k + 2] = v.z; xrow[k + 3] = v.w;
        if (k + 0 < n) m = fmaxf(m, v.x);
        if (k + 1 < n) m = fmaxf(m, v.y);
        if (k + 2 < n) m = fmaxf(m, v.z);
        if (k + 3 < n) m = fmaxf(m, v.w);
    }
    #pragma unroll
    for (int o = 16; o > 0; o >>= 1) m = fmaxf(m, __shfl_xor_sync(0xFFFFFFFFu, m, o));

    float sum = 0.f;
    for (int k = lane * 4; k < n; k += 128) {
        #pragma unroll
        for (int j = 0; j < 4; j++) {
            const float e = (k + j < n) ? __expf(xrow[k + j] - m) : 0.f;
            xrow[k + j] = e;
            sum += e;
        }
    }
    #pragma unroll
    for (int o = 16; o > 0; o >>= 1) sum += __shfl_xor_sync(0xFFFFFFFFu, sum, o);
    const float inv = 1.0f / sum;

    __nv_bfloat16* ph = g_P_hi + ((size_t)h * TT + q) * TT;
    __nv_bfloat16* pl = g_P_lo + ((size_t)h * TT + q) * TT;
    for (int k = lane * 4; k < npad; k += 128) {
        __nv_bfloat162 hv0, lv0, hv1, lv1;
        #pragma unroll
        for (int j = 0; j < 4; j++) {
            const float p = (k + j < n) ? xrow[k + j] * inv : 0.f;
            const __nv_bfloat16 hb = __float2bfloat16(p);
            const __nv_bfloat16 lb = __float2bfloat16(p - __bfloat162float(hb));
            if (j == 0) { hv0.x = hb; lv0.x = lb; }
            if (j == 1) { hv0.y = hb; lv0.y = lb; }
            if (j == 2) { hv1.x = hb; lv1.x = lb; }
            if (j == 3) { hv1.y = hb; lv1.y = lb; }
        }
        *(__nv_bfloat162*)(ph + k)     = hv0;
        *(__nv_bfloat162*)(ph + k + 2) = hv1;
        *(__nv_bfloat162*)(pl + k)     = lv0;
        *(__nv_bfloat162*)(pl + k + 2) = lv1;
    }
}

// ============================================================
extern "C" void kernel_launch(void* const* d_in, const int* in_sizes, int n_in,
                              void* d_out, int out_size)
{
    const int*   positions = (const int*)d_in[0];
    const float* hidden    = (const float*)d_in[1];
    const float* Wqkv      = (const float*)d_in[2];
    const float* Wo        = (const float*)d_in[3];
    float*       out       = (float*)d_out;

    float *S, *pvp;
    __nv_bfloat16 *hh, *hl, *wqh, *wql, *woh, *wol, *Qh, *Ql, *Kh, *Kl, *Vth, *Vtl,
                  *Ph, *Pl, *Ath, *Atl;
    cudaGetSymbolAddress((void**)&S,   g_S);
    cudaGetSymbolAddress((void**)&pvp, g_pv_part);
    cudaGetSymbolAddress((void**)&hh,  g_hid_hi);  cudaGetSymbolAddress((void**)&hl,  g_hid_lo);
    cudaGetSymbolAddress((void**)&wqh, g_wqkv_hi); cudaGetSymbolAddress((void**)&wql, g_wqkv_lo);
    cudaGetSymbolAddress((void**)&woh, g_wo_hi);   cudaGetSymbolAddress((void**)&wol, g_wo_lo);
    cudaGetSymbolAddress((void**)&Qh,  g_Q_hi);    cudaGetSymbolAddress((void**)&Ql,  g_Q_lo);
    cudaGetSymbolAddress((void**)&Kh,  g_K_hi);    cudaGetSymbolAddress((void**)&Kl,  g_K_lo);
    cudaGetSymbolAddress((void**)&Vth, g_Vt_hi);   cudaGetSymbolAddress((void**)&Vtl, g_Vt_lo);
    cudaGetSymbolAddress((void**)&Ph,  g_P_hi);    cudaGetSymbolAddress((void**)&Pl,  g_P_lo);
    cudaGetSymbolAddress((void**)&Ath, g_attn_hi); cudaGetSymbolAddress((void**)&Atl, g_attn_lo);

    const int SMEM_MT2 = NSTG * (2 * 8192 + 16384);   // 98304

    cudaFuncSetAttribute(gemm_mma3<false, false, 2, 4, 1>, cudaFuncAttributeMaxDynamicSharedMemorySize, SMEM_MT2);
    cudaFuncSetAttribute(gemm_mma3<true,  false, 2, 1, 2>, cudaFuncAttributeMaxDynamicSharedMemorySize, SMEM_MT2);
    cudaFuncSetAttribute(gemm_mma3<false, true,  2, 4, 1>, cudaFuncAttributeMaxDynamicSharedMemorySize, SMEM_MT2);
    cudaFuncSetAttribute(gemm_mma3<false, false, 2, 1, 1>, cudaFuncAttributeMaxDynamicSharedMemorySize, SMEM_MT2);
    cudaFuncSetAttribute(softmax_planes, cudaFuncAttributeMaxDynamicSharedMemorySize, 65536);

    // 0) fp32 -> bf16 hi/lo planes (single fused launch)
    {
        int n0 = TT * HID / 4, n1 = QKVN * HID / 4, n2 = HID * QS / 4;
        int tot = n0 + n1 + n2;
        conv_all<<<(tot + 255) / 256, 256>>>(hidden, hh, hl, n0,
                                             Wqkv, wqh, wql, n1,
                                             Wo, woh, wol, n2);
    }

    // 1) qkv partials = hidden @ Wqkv^T (split-K x4, 1280 CTAs)
    gemm_mma3<false, false, 2, 4, 1><<<dim3(QKVN / 128, TT / 128, 4), 256, SMEM_MT2>>>(
        hh, hl, wqh, wql, S, nullptr, nullptr,
        HID, HID, HID, QKVN, 1.0f, 0, 0, 0, (size_t)TT * QKVN);

    // 2) RoPE + 4-partial sum + plane split (V transposed)
    rope_split_planes<<<dim3(TT, 10), 128>>>(positions);

    // 3) scores = scale * Q @ K^T (causal, XPAIR: 256-col CTAs, one warmup) -> g_S
    gemm_mma3<true, false, 2, 1, 2><<<dim3(TT / 256, TT / 128, NHEADS), 256, SMEM_MT2>>>(
        Qh, Ql, Kh, Kl, S, nullptr, nullptr,
        HD, HD, HD, TT, SCALING, (size_t)TT * HD, 0, (size_t)TT * TT, 0);

    // 4) softmax -> P planes
    softmax_planes<<<dim3(TT / 8, NHEADS), 256, 65536>>>();

    // 5) attn partials = P @ Vt^T (block-causal K, split-K x4, big tiles first)
    gemm_mma3<false, true, 2, 4, 1><<<dim3(HD / 128, TT / 128, NHEADS * 4), 256, SMEM_MT2>>>(
        Ph, Pl, Vth, Vtl, pvp, nullptr, nullptr,
        TT, TT, TT, QS, 1.0f, (size_t)TT * TT, 0, (size_t)HD, (size_t)TT * QS);

    // 5b) attn = sum of 4 partials -> bf16 hi/lo planes
    {
        int n4 = TT * QS / 4;
        const size_t P = (size_t)TT * QS;
        addconv_planes4<<<(n4 + 255) / 256, 256>>>(pvp, pvp + P, pvp + 2 * P, pvp + 3 * P,
                                                   Ath, Atl, n4);
    }

    // 6) out = attn @ Wo^T
    gemm_mma3<false, false, 2, 1, 1><<<dim3(HID / 128, TT / 128, 1), 256, SMEM_MT2>>>(
        Ath, Atl, woh, wol, out, nullptr, nullptr,
        QS, QS, QS, HID, 1.0f, 0, 0, 0, 0);
}